// round 14
// baseline (speedup 1.0000x reference)
#include <cuda_runtime.h>
#include <cuda_fp16.h>
#include <cstdint>
#include <cstddef>

#define N_TOKS  8192
#define DIN     1024
#define DHID    4096
#define DOUT    1024
#define NEXP    12
#define TOPK    4
#define CAP     4096

// ---------------- scratch (device globals) ----------------
__device__ int    g_cnt[NEXP];
__device__ int    g_tok[NEXP * CAP];
__device__ int    g_slot[N_TOKS * TOPK];
__device__ float  g_tw[N_TOKS * TOPK];
__device__ __half g_xh [(size_t)N_TOKS * DIN];
__device__ __half g_W1h[(size_t)NEXP * DIN * DHID];
__device__ __half g_W2h[(size_t)NEXP * DHID * DOUT];
__device__ __half g_h  [(size_t)NEXP * CAP * DHID];
__device__ float  g_y  [(size_t)NEXP * CAP * DOUT];

// ---------------- helpers ----------------
static __device__ __forceinline__ uint32_t sptr(const void* p) {
    return (uint32_t)__cvta_generic_to_shared(p);
}
static __device__ __forceinline__ void cp16(uint32_t s, const void* g) {
    asm volatile("cp.async.cg.shared.global [%0], [%1], 16;" :: "r"(s), "l"(g));
}
static __device__ __forceinline__ void cp_commit() {
    asm volatile("cp.async.commit_group;");
}
template <int N>
static __device__ __forceinline__ void cp_wait() {
    asm volatile("cp.async.wait_group %0;" :: "n"(N));
}
static __device__ __forceinline__ void ldsm4(uint32_t& r0, uint32_t& r1,
                                             uint32_t& r2, uint32_t& r3, uint32_t a) {
    asm volatile("ldmatrix.sync.aligned.m8n8.x4.shared.b16 {%0,%1,%2,%3}, [%4];"
                 : "=r"(r0), "=r"(r1), "=r"(r2), "=r"(r3) : "r"(a));
}
static __device__ __forceinline__ void ldsm4t(uint32_t& r0, uint32_t& r1,
                                              uint32_t& r2, uint32_t& r3, uint32_t a) {
    asm volatile("ldmatrix.sync.aligned.m8n8.x4.trans.shared.b16 {%0,%1,%2,%3}, [%4];"
                 : "=r"(r0), "=r"(r1), "=r"(r2), "=r"(r3) : "r"(a));
}
static __device__ __forceinline__ void mma16816(float* c, const uint32_t* a,
                                                const uint32_t* b) {
    asm volatile(
        "mma.sync.aligned.m16n8k16.row.col.f32.f16.f16.f32 "
        "{%0,%1,%2,%3}, {%4,%5,%6,%7}, {%8,%9}, {%0,%1,%2,%3};"
        : "+f"(c[0]), "+f"(c[1]), "+f"(c[2]), "+f"(c[3])
        : "r"(a[0]), "r"(a[1]), "r"(a[2]), "r"(a[3]), "r"(b[0]), "r"(b[1]));
}

// ---------------- kernel 0: zero counters ----------------
__global__ void k_zero() {
    if (threadIdx.x < NEXP) g_cnt[threadIdx.x] = 0;
}

// ---------------- fused fp32->fp16 conversion of x, W1, W2 ----------------
static constexpr size_t NX  = (size_t)N_TOKS * DIN;
static constexpr size_t NW1 = (size_t)NEXP * DIN * DHID;
static constexpr size_t NW2 = (size_t)NEXP * DHID * DOUT;
__global__ void k_conv(const float* __restrict__ x, const float* __restrict__ W1,
                       const float* __restrict__ W2) {
    size_t i = ((size_t)blockIdx.x * 256 + threadIdx.x) * 8;
    const float* in;
    __half* out;
    if (i < NX)            { in = x  + i;              out = g_xh  + i; }
    else if (i < NX + NW1) { in = W1 + (i - NX);       out = g_W1h + (i - NX); }
    else                   { in = W2 + (i - NX - NW1); out = g_W2h + (i - NX - NW1); }
    float4 a = *(const float4*)(in);
    float4 b = *(const float4*)(in + 4);
    __half2 h0 = __floats2half2_rn(a.x, a.y);
    __half2 h1 = __floats2half2_rn(a.z, a.w);
    __half2 h2 = __floats2half2_rn(b.x, b.y);
    __half2 h3 = __floats2half2_rn(b.z, b.w);
    uint4 o;
    o.x = *(uint32_t*)&h0; o.y = *(uint32_t*)&h1;
    o.z = *(uint32_t*)&h2; o.w = *(uint32_t*)&h3;
    *(uint4*)(out) = o;
}

// ---------------- gate: logits, top-4, softmax, routing ----------------
__global__ void k_gate(const float* __restrict__ x, const float* __restrict__ Wg,
                       const float* __restrict__ bg) {
    extern __shared__ float sWg[];
    __shared__ float sLog[8][NEXP];
    __shared__ int   sCnt[NEXP];
    __shared__ int   sBase[NEXP];
    __shared__ int   sE[8][TOPK];
    __shared__ int   sL[8][TOPK];
    __shared__ float sW[8][TOPK];

    int tid = threadIdx.x;
    for (int i = tid; i < DIN * NEXP / 4; i += 256)
        ((float4*)sWg)[i] = ((const float4*)Wg)[i];
    if (tid < NEXP) sCnt[tid] = 0;
    __syncthreads();

    int wp = tid >> 5, lane = tid & 31;
    int n = blockIdx.x * 8 + wp;

    float xv[32];
#pragma unroll
    for (int i = 0; i < 32; i++)
        xv[i] = x[(size_t)n * DIN + i * 32 + lane];

#pragma unroll
    for (int e = 0; e < NEXP; e++) {
        float p = 0.f;
#pragma unroll
        for (int i = 0; i < 32; i++)
            p += xv[i] * sWg[(i * 32 + lane) * NEXP + e];
#pragma unroll
        for (int o = 16; o > 0; o >>= 1)
            p += __shfl_xor_sync(0xffffffffu, p, o);
        if (lane == 0) sLog[wp][e] = p + bg[e];
    }
    __syncwarp();

    if (lane == 0) {
        float v[NEXP];
#pragma unroll
        for (int e = 0; e < NEXP; e++) v[e] = sLog[wp][e];
        float bv[TOPK]; int bi[TOPK];
#pragma unroll
        for (int k = 0; k < TOPK; k++) {
            float best = -1e30f; int bj = 0;
#pragma unroll
            for (int e = 0; e < NEXP; e++)
                if (v[e] > best) { best = v[e]; bj = e; }
            bv[k] = best; bi[k] = bj; v[bj] = -1e30f;
        }
        float m = bv[0], s = 0.f, ew[TOPK];
#pragma unroll
        for (int k = 0; k < TOPK; k++) { ew[k] = expf(bv[k] - m); s += ew[k]; }
        float inv = 1.0f / s;
#pragma unroll
        for (int k = 0; k < TOPK; k++) {
            int e = bi[k];
            int loc = atomicAdd(&sCnt[e], 1);
            sE[wp][k] = e; sL[wp][k] = loc; sW[wp][k] = ew[k] * inv;
        }
    }
    __syncthreads();
    if (tid < NEXP) sBase[tid] = atomicAdd(&g_cnt[tid], sCnt[tid]);
    __syncthreads();
    if (lane == 0) {
#pragma unroll
        for (int k = 0; k < TOPK; k++) {
            int e = sE[wp][k];
            int idx = sBase[e] + sL[wp][k];
            g_tok[e * CAP + idx] = n;
            g_slot[n * TOPK + k] = e * CAP + idx;
            g_tw[n * TOPK + k]   = sW[wp][k];
        }
    }
}

// ---- fp16 mma.sync grouped GEMM: TILES M-tiles/CTA, 128x128x64, 128 thr, 3-stage ring ----
static constexpr int NSTG     = 3;
static constexpr int AS_LD    = 72;                 // halves
static constexpr int BS_LD    = 136;                // halves
static constexpr int AS_STG_H = 128 * AS_LD;
static constexpr int BS_STG_H = 64 * BS_LD;
static constexpr int AS_STG_B = AS_STG_H * 2;       // 18432
static constexpr int BS_STG_B = BS_STG_H * 2;       // 17408
static constexpr int AS_OFF   = 0;
static constexpr int BS_OFF   = NSTG * AS_STG_B;                // 55296
static constexpr int TOK_OFF  = BS_OFF + NSTG * BS_STG_B;       // 107520
static constexpr int SMEM_GM  = TOK_OFF + 1024 + 256;           // 108800 (2 CTA/SM)

template <int KD, int NT, bool GATHER, bool RELU, int TILES>
__global__ void __launch_bounds__(128, 2)
k_gemm_h(const __half* __restrict__ W, const float* __restrict__ bias) {
    extern __shared__ char smem[];
    __half* As   = (__half*)(smem + AS_OFF);
    __half* Bs   = (__half*)(smem + BS_OFF);
    int*    sTok = (int*)(smem + TOK_OFF);

    int e    = blockIdx.z;
    int cnt  = g_cnt[e];
    int row0 = blockIdx.y * (128 * TILES);
    if (row0 >= cnt) return;
    int n0   = blockIdx.x * 128;
    int tid  = threadIdx.x;

    const __half* Ain = GATHER ? (const __half*)g_xh : (const __half*)g_h;

    if (GATHER) {
#pragma unroll
        for (int t = 0; t < TILES; t++) {
            int r = row0 + t * 128 + tid;
            sTok[t * 128 + tid] = (r < cnt) ? g_tok[e * CAP + r] : g_tok[e * CAP];
        }
        __syncthreads();
    }

    const __half* Wp = W + (size_t)e * KD * NT + n0;

    constexpr int NKT = KD / 64;
    // global pipeline step gq in [0, TILES*NKT): tile = gq/NKT, kt = gq%NKT
    auto loadStage = [&](int gq) {
        int buf  = gq % NSTG;
        int tile = gq / NKT;
        int kt   = gq % NKT;
        int k0   = kt * 64;
        int rb   = row0 + tile * 128;
#pragma unroll
        for (int i = 0; i < 8; i++) {
            int c = tid + i * 128;
            int r = c >> 3, sg = (c & 7) * 8;
            const __half* g = GATHER
                ? (Ain + (size_t)sTok[tile * 128 + r] * KD + k0 + sg)
                : (Ain + ((size_t)e * CAP + rb + r) * KD + k0 + sg);
            cp16(sptr(As + buf * AS_STG_H + r * AS_LD + sg), g);
        }
#pragma unroll
        for (int i = 0; i < 8; i++) {
            int c = tid + i * 128;
            int r = c >> 4, col = (c & 15) * 8;
            cp16(sptr(Bs + buf * BS_STG_H + r * BS_LD + col),
                 Wp + (size_t)(k0 + r) * NT + col);
        }
    };

    int wp = tid >> 5, lane = tid & 31;
    int wm = wp & 1, wn = wp >> 1;       // 2x2 warp grid; warp tile 64x64

    uint32_t aBase = sptr(As) +
        (uint32_t)(((wm * 64 + (lane & 15)) * AS_LD + (lane >> 4) * 8) * 2);
    uint32_t bBase = sptr(Bs) +
        (uint32_t)(((((lane >> 3) & 1) * 8 + (lane & 7)) * BS_LD
                    + wn * 64 + (lane >> 4) * 8) * 2);

    float c[4][8][4];
#pragma unroll
    for (int i = 0; i < 4; i++)
#pragma unroll
        for (int j = 0; j < 8; j++)
#pragma unroll
            for (int q = 0; q < 4; q++) c[i][j][q] = 0.f;

    uint32_t Ar[2][16], Br[2][16];

    auto ldA = [&](uint32_t* a, int buf, int ks) {
        uint32_t base = aBase + buf * AS_STG_B + ks * 32;
#pragma unroll
        for (int mi = 0; mi < 4; mi++)
            ldsm4(a[mi * 4 + 0], a[mi * 4 + 1], a[mi * 4 + 2], a[mi * 4 + 3],
                  base + mi * 16 * AS_LD * 2);
    };
    auto ldB = [&](uint32_t* b, int buf, int ks) {
        uint32_t base = bBase + buf * BS_STG_B + ks * 16 * BS_LD * 2;
#pragma unroll
        for (int nb = 0; nb < 4; nb++) {
            uint32_t r0, r1, r2, r3;
            ldsm4t(r0, r1, r2, r3, base + nb * 32);
            b[(nb * 2) * 2 + 0] = r0; b[(nb * 2) * 2 + 1] = r1;
            b[(nb * 2 + 1) * 2 + 0] = r2; b[(nb * 2 + 1) * 2 + 1] = r3;
        }
    };
    auto mmaAll = [&](const uint32_t* a, const uint32_t* b) {
#pragma unroll
        for (int mi = 0; mi < 4; mi++)
#pragma unroll
            for (int nj = 0; nj < 8; nj++)
                mma16816(c[mi][nj], a + mi * 4, b + nj * 2);
    };

    // register-direct epilogue: no smem, no block sync; overlaps in-flight loads
    auto epilogue = [&](int tile) {
        int rbase = row0 + tile * 128 + wm * 64;
        const float* bp = bias + (size_t)e * NT + n0 + wn * 64;
        int g = lane >> 2, tg = lane & 3;
#pragma unroll
        for (int mi = 0; mi < 4; mi++) {
#pragma unroll
            for (int nj = 0; nj < 8; nj++) {
                int col = nj * 8 + tg * 2;
                float b0 = __ldg(bp + col), b1 = __ldg(bp + col + 1);
                float v0 = c[mi][nj][0] + b0, v1 = c[mi][nj][1] + b1;
                float v2 = c[mi][nj][2] + b0, v3 = c[mi][nj][3] + b1;
                if (RELU) {
                    v0 = fmaxf(v0, 0.f); v1 = fmaxf(v1, 0.f);
                    v2 = fmaxf(v2, 0.f); v3 = fmaxf(v3, 0.f);
                }
                int r0 = rbase + mi * 16 + g;
                size_t cbase = (size_t)e * CAP;
                size_t coloff = (size_t)n0 + wn * 64 + col;
                if (r0 < cnt) {
                    if (RELU) {
                        __half2 h = __floats2half2_rn(v0, v1);
                        *(uint32_t*)(g_h + (cbase + r0) * NT + coloff) = *(uint32_t*)&h;
                    } else {
                        float2 f = {v0, v1};
                        *(float2*)(g_y + (cbase + r0) * NT + coloff) = f;
                    }
                }
                if (r0 + 8 < cnt) {
                    if (RELU) {
                        __half2 h = __floats2half2_rn(v2, v3);
                        *(uint32_t*)(g_h + (cbase + r0 + 8) * NT + coloff) = *(uint32_t*)&h;
                    } else {
                        float2 f = {v2, v3};
                        *(float2*)(g_y + (cbase + r0 + 8) * NT + coloff) = f;
                    }
                }
            }
        }
#pragma unroll
        for (int i = 0; i < 4; i++)
#pragma unroll
            for (int j = 0; j < 8; j++)
#pragma unroll
                for (int q = 0; q < 4; q++) c[i][j][q] = 0.f;
    };

    const int TT = TILES * NKT;
    loadStage(0); cp_commit();
    loadStage(1); cp_commit();

    for (int gq = 0; gq < TT; gq++) {
        if (gq + 1 < TT) cp_wait<1>(); else cp_wait<0>();
        __syncthreads();

        int stg = gq % NSTG;
        // head fragments FIRST: ldsm latency + first MMAs overlap the LDGSTS issue below
        ldA(Ar[0], stg, 0); ldB(Br[0], stg, 0);

        if (gq + 2 < TT) { loadStage(gq + 2); cp_commit(); }

#pragma unroll
        for (int ks = 0; ks < 4; ks++) {
            if (ks < 3) {
                ldA(Ar[(ks + 1) & 1], stg, ks + 1);
                ldB(Br[(ks + 1) & 1], stg, ks + 1);
            }
            mmaAll(Ar[ks & 1], Br[ks & 1]);
        }
        if ((gq & (NKT - 1)) == NKT - 1) epilogue(gq / NKT);
    }
}

// ---------------- weighted combine ----------------
__global__ void k_combine(float* __restrict__ out) {
    int n = blockIdx.x;
    int c = threadIdx.x * 4;
    int   s0 = g_slot[n * TOPK + 0], s1 = g_slot[n * TOPK + 1];
    int   s2 = g_slot[n * TOPK + 2], s3 = g_slot[n * TOPK + 3];
    float w0 = g_tw[n * TOPK + 0],  w1 = g_tw[n * TOPK + 1];
    float w2 = g_tw[n * TOPK + 2],  w3 = g_tw[n * TOPK + 3];
    float4 y0 = *(const float4*)(g_y + (size_t)s0 * DOUT + c);
    float4 y1 = *(const float4*)(g_y + (size_t)s1 * DOUT + c);
    float4 y2 = *(const float4*)(g_y + (size_t)s2 * DOUT + c);
    float4 y3 = *(const float4*)(g_y + (size_t)s3 * DOUT + c);
    float4 r;
    r.x = w0 * y0.x + w1 * y1.x + w2 * y2.x + w3 * y3.x;
    r.y = w0 * y0.y + w1 * y1.y + w2 * y2.y + w3 * y3.y;
    r.z = w0 * y0.z + w1 * y1.z + w2 * y2.z + w3 * y3.z;
    r.w = w0 * y0.w + w1 * y1.w + w2 * y2.w + w3 * y3.w;
    *(float4*)(out + (size_t)n * DOUT + c) = r;
}

// ---------------- launch ----------------
extern "C" void kernel_launch(void* const* d_in, const int* in_sizes, int n_in,
                              void* d_out, int out_size) {
    const float* x  = (const float*)d_in[0];
    const float* W1 = (const float*)d_in[1];
    const float* b1 = (const float*)d_in[2];
    const float* W2 = (const float*)d_in[3];
    const float* b2 = (const float*)d_in[4];
    const float* Wg = (const float*)d_in[5];
    const float* bg = (const float*)d_in[6];
    float* out = (float*)d_out;

    const int SMEM_GATE = DIN * NEXP * (int)sizeof(float);

    cudaFuncSetAttribute((const void*)k_gate,
                         cudaFuncAttributeMaxDynamicSharedMemorySize, SMEM_GATE);
    cudaFuncSetAttribute((const void*)k_gemm_h<DIN, DHID, true, true, 2>,
                         cudaFuncAttributeMaxDynamicSharedMemorySize, SMEM_GM);
    cudaFuncSetAttribute((const void*)k_gemm_h<DHID, DOUT, false, false, 1>,
                         cudaFuncAttributeMaxDynamicSharedMemorySize, SMEM_GM);

    __half* w1h = nullptr; cudaGetSymbolAddress((void**)&w1h, g_W1h);
    __half* w2h = nullptr; cudaGetSymbolAddress((void**)&w2h, g_W2h);

    // harness prepends 2 launches; ncu -s 5 -c 1 profiles our launch #3 = gemm1
    k_zero<<<1, 32>>>();
    k_gate<<<N_TOKS / 8, 256, SMEM_GATE>>>(x, Wg, bg);
    k_conv<<<(int)((NX + NW1 + NW2) / (256 * 8)), 256>>>(x, W1, W2);
    k_gemm_h<DIN, DHID, true, true, 2>
        <<<dim3(DHID / 128, CAP / 256, NEXP), 128, SMEM_GM>>>(w1h, b1);
    k_gemm_h<DHID, DOUT, false, false, 1>
        <<<dim3(DOUT / 128, CAP / 128, NEXP), 128, SMEM_GM>>>(w2h, b2);
    k_combine<<<N_TOKS, 256>>>(out);
}

// round 15
// speedup vs baseline: 1.0539x; 1.0539x over previous
#include <cuda_runtime.h>
#include <cuda_fp16.h>
#include <cstdint>
#include <cstddef>

#define N_TOKS  8192
#define DIN     1024
#define DHID    4096
#define DOUT    1024
#define NEXP    12
#define TOPK    4
#define CAP     4096

// ---------------- scratch (device globals) ----------------
__device__ int    g_cnt[NEXP];
__device__ int    g_tok[NEXP * CAP];
__device__ int    g_slot[N_TOKS * TOPK];
__device__ float  g_tw[N_TOKS * TOPK];
__device__ __half g_xh [(size_t)N_TOKS * DIN];
__device__ __half g_W1h[(size_t)NEXP * DIN * DHID];
__device__ __half g_W2h[(size_t)NEXP * DHID * DOUT];
__device__ __half g_h  [(size_t)NEXP * CAP * DHID];
__device__ __half g_y  [(size_t)NEXP * CAP * DOUT];   // fp16 now

// ---------------- helpers ----------------
static __device__ __forceinline__ uint32_t sptr(const void* p) {
    return (uint32_t)__cvta_generic_to_shared(p);
}
static __device__ __forceinline__ void cp16(uint32_t s, const void* g) {
    asm volatile("cp.async.cg.shared.global [%0], [%1], 16;" :: "r"(s), "l"(g));
}
static __device__ __forceinline__ void cp_commit() {
    asm volatile("cp.async.commit_group;");
}
template <int N>
static __device__ __forceinline__ void cp_wait() {
    asm volatile("cp.async.wait_group %0;" :: "n"(N));
}
static __device__ __forceinline__ void ldsm4(uint32_t& r0, uint32_t& r1,
                                             uint32_t& r2, uint32_t& r3, uint32_t a) {
    asm volatile("ldmatrix.sync.aligned.m8n8.x4.shared.b16 {%0,%1,%2,%3}, [%4];"
                 : "=r"(r0), "=r"(r1), "=r"(r2), "=r"(r3) : "r"(a));
}
static __device__ __forceinline__ void ldsm4t(uint32_t& r0, uint32_t& r1,
                                              uint32_t& r2, uint32_t& r3, uint32_t a) {
    asm volatile("ldmatrix.sync.aligned.m8n8.x4.trans.shared.b16 {%0,%1,%2,%3}, [%4];"
                 : "=r"(r0), "=r"(r1), "=r"(r2), "=r"(r3) : "r"(a));
}
static __device__ __forceinline__ void mma16816(float* c, const uint32_t* a,
                                                const uint32_t* b) {
    asm volatile(
        "mma.sync.aligned.m16n8k16.row.col.f32.f16.f16.f32 "
        "{%0,%1,%2,%3}, {%4,%5,%6,%7}, {%8,%9}, {%0,%1,%2,%3};"
        : "+f"(c[0]), "+f"(c[1]), "+f"(c[2]), "+f"(c[3])
        : "r"(a[0]), "r"(a[1]), "r"(a[2]), "r"(a[3]), "r"(b[0]), "r"(b[1]));
}

// ---------------- kernel 0: zero counters ----------------
__global__ void k_zero() {
    if (threadIdx.x < NEXP) g_cnt[threadIdx.x] = 0;
}

// ---------------- fused fp32->fp16 conversion of x, W1, W2 ----------------
static constexpr size_t NX  = (size_t)N_TOKS * DIN;
static constexpr size_t NW1 = (size_t)NEXP * DIN * DHID;
static constexpr size_t NW2 = (size_t)NEXP * DHID * DOUT;
__global__ void k_conv(const float* __restrict__ x, const float* __restrict__ W1,
                       const float* __restrict__ W2) {
    size_t i = ((size_t)blockIdx.x * 256 + threadIdx.x) * 8;
    const float* in;
    __half* out;
    if (i < NX)            { in = x  + i;              out = g_xh  + i; }
    else if (i < NX + NW1) { in = W1 + (i - NX);       out = g_W1h + (i - NX); }
    else                   { in = W2 + (i - NX - NW1); out = g_W2h + (i - NX - NW1); }
    float4 a = *(const float4*)(in);
    float4 b = *(const float4*)(in + 4);
    __half2 h0 = __floats2half2_rn(a.x, a.y);
    __half2 h1 = __floats2half2_rn(a.z, a.w);
    __half2 h2 = __floats2half2_rn(b.x, b.y);
    __half2 h3 = __floats2half2_rn(b.z, b.w);
    uint4 o;
    o.x = *(uint32_t*)&h0; o.y = *(uint32_t*)&h1;
    o.z = *(uint32_t*)&h2; o.w = *(uint32_t*)&h3;
    *(uint4*)(out) = o;
}

// ---------------- gate: logits, top-4, softmax, routing ----------------
__global__ void k_gate(const float* __restrict__ x, const float* __restrict__ Wg,
                       const float* __restrict__ bg) {
    extern __shared__ float sWg[];
    __shared__ float sLog[8][NEXP];
    __shared__ int   sCnt[NEXP];
    __shared__ int   sBase[NEXP];
    __shared__ int   sE[8][TOPK];
    __shared__ int   sL[8][TOPK];
    __shared__ float sW[8][TOPK];

    int tid = threadIdx.x;
    for (int i = tid; i < DIN * NEXP / 4; i += 256)
        ((float4*)sWg)[i] = ((const float4*)Wg)[i];
    if (tid < NEXP) sCnt[tid] = 0;
    __syncthreads();

    int wp = tid >> 5, lane = tid & 31;
    int n = blockIdx.x * 8 + wp;

    float xv[32];
#pragma unroll
    for (int i = 0; i < 32; i++)
        xv[i] = x[(size_t)n * DIN + i * 32 + lane];

#pragma unroll
    for (int e = 0; e < NEXP; e++) {
        float p = 0.f;
#pragma unroll
        for (int i = 0; i < 32; i++)
            p += xv[i] * sWg[(i * 32 + lane) * NEXP + e];
#pragma unroll
        for (int o = 16; o > 0; o >>= 1)
            p += __shfl_xor_sync(0xffffffffu, p, o);
        if (lane == 0) sLog[wp][e] = p + bg[e];
    }
    __syncwarp();

    if (lane == 0) {
        float v[NEXP];
#pragma unroll
        for (int e = 0; e < NEXP; e++) v[e] = sLog[wp][e];
        float bv[TOPK]; int bi[TOPK];
#pragma unroll
        for (int k = 0; k < TOPK; k++) {
            float best = -1e30f; int bj = 0;
#pragma unroll
            for (int e = 0; e < NEXP; e++)
                if (v[e] > best) { best = v[e]; bj = e; }
            bv[k] = best; bi[k] = bj; v[bj] = -1e30f;
        }
        float m = bv[0], s = 0.f, ew[TOPK];
#pragma unroll
        for (int k = 0; k < TOPK; k++) { ew[k] = expf(bv[k] - m); s += ew[k]; }
        float inv = 1.0f / s;
#pragma unroll
        for (int k = 0; k < TOPK; k++) {
            int e = bi[k];
            int loc = atomicAdd(&sCnt[e], 1);
            sE[wp][k] = e; sL[wp][k] = loc; sW[wp][k] = ew[k] * inv;
        }
    }
    __syncthreads();
    if (tid < NEXP) sBase[tid] = atomicAdd(&g_cnt[tid], sCnt[tid]);
    __syncthreads();
    if (lane == 0) {
#pragma unroll
        for (int k = 0; k < TOPK; k++) {
            int e = sE[wp][k];
            int idx = sBase[e] + sL[wp][k];
            g_tok[e * CAP + idx] = n;
            g_slot[n * TOPK + k] = e * CAP + idx;
            g_tw[n * TOPK + k]   = sW[wp][k];
        }
    }
}

// ---- fp16 mma.sync grouped GEMM: TILES M-tiles/CTA, 128x128x64, 128 thr, 3-stage ring ----
static constexpr int NSTG     = 3;
static constexpr int AS_LD    = 72;                 // halves
static constexpr int BS_LD    = 136;                // halves
static constexpr int AS_STG_H = 128 * AS_LD;
static constexpr int BS_STG_H = 64 * BS_LD;
static constexpr int AS_STG_B = AS_STG_H * 2;       // 18432
static constexpr int BS_STG_B = BS_STG_H * 2;       // 17408
static constexpr int AS_OFF   = 0;
static constexpr int BS_OFF   = NSTG * AS_STG_B;                // 55296
static constexpr int TOK_OFF  = BS_OFF + NSTG * BS_STG_B;       // 107520
static constexpr int SMEM_GM  = TOK_OFF + 1024 + 256;           // 108800 (2 CTA/SM)

template <int KD, int NT, bool GATHER, bool RELU, int TILES>
__global__ void __launch_bounds__(128, 2)
k_gemm_h(const __half* __restrict__ W, const float* __restrict__ bias) {
    extern __shared__ char smem[];
    __half* As   = (__half*)(smem + AS_OFF);
    __half* Bs   = (__half*)(smem + BS_OFF);
    int*    sTok = (int*)(smem + TOK_OFF);

    int e    = blockIdx.z;
    int cnt  = g_cnt[e];
    int row0 = blockIdx.y * (128 * TILES);
    if (row0 >= cnt) return;
    int n0   = blockIdx.x * 128;
    int tid  = threadIdx.x;

    const __half* Ain = GATHER ? (const __half*)g_xh : (const __half*)g_h;

    if (GATHER) {
#pragma unroll
        for (int t = 0; t < TILES; t++) {
            int r = row0 + t * 128 + tid;
            sTok[t * 128 + tid] = (r < cnt) ? g_tok[e * CAP + r] : g_tok[e * CAP];
        }
        __syncthreads();
    }

    const __half* Wp = W + (size_t)e * KD * NT + n0;

    constexpr int NKT = KD / 64;
    // global pipeline step gq in [0, TILES*NKT): tile = gq/NKT, kt = gq%NKT
    auto loadStage = [&](int gq) {
        int buf  = gq % NSTG;
        int tile = gq / NKT;
        int kt   = gq % NKT;
        int k0   = kt * 64;
        int rb   = row0 + tile * 128;
#pragma unroll
        for (int i = 0; i < 8; i++) {
            int c = tid + i * 128;
            int r = c >> 3, sg = (c & 7) * 8;
            const __half* g = GATHER
                ? (Ain + (size_t)sTok[tile * 128 + r] * KD + k0 + sg)
                : (Ain + ((size_t)e * CAP + rb + r) * KD + k0 + sg);
            cp16(sptr(As + buf * AS_STG_H + r * AS_LD + sg), g);
        }
#pragma unroll
        for (int i = 0; i < 8; i++) {
            int c = tid + i * 128;
            int r = c >> 4, col = (c & 15) * 8;
            cp16(sptr(Bs + buf * BS_STG_H + r * BS_LD + col),
                 Wp + (size_t)(k0 + r) * NT + col);
        }
    };

    int wp = tid >> 5, lane = tid & 31;
    int wm = wp & 1, wn = wp >> 1;       // 2x2 warp grid; warp tile 64x64

    uint32_t aBase = sptr(As) +
        (uint32_t)(((wm * 64 + (lane & 15)) * AS_LD + (lane >> 4) * 8) * 2);
    uint32_t bBase = sptr(Bs) +
        (uint32_t)(((((lane >> 3) & 1) * 8 + (lane & 7)) * BS_LD
                    + wn * 64 + (lane >> 4) * 8) * 2);

    float c[4][8][4];
#pragma unroll
    for (int i = 0; i < 4; i++)
#pragma unroll
        for (int j = 0; j < 8; j++)
#pragma unroll
            for (int q = 0; q < 4; q++) c[i][j][q] = 0.f;

    uint32_t Ar[2][16], Br[2][16];

    auto ldA = [&](uint32_t* a, int buf, int ks) {
        uint32_t base = aBase + buf * AS_STG_B + ks * 32;
#pragma unroll
        for (int mi = 0; mi < 4; mi++)
            ldsm4(a[mi * 4 + 0], a[mi * 4 + 1], a[mi * 4 + 2], a[mi * 4 + 3],
                  base + mi * 16 * AS_LD * 2);
    };
    auto ldB = [&](uint32_t* b, int buf, int ks) {
        uint32_t base = bBase + buf * BS_STG_B + ks * 16 * BS_LD * 2;
#pragma unroll
        for (int nb = 0; nb < 4; nb++) {
            uint32_t r0, r1, r2, r3;
            ldsm4t(r0, r1, r2, r3, base + nb * 32);
            b[(nb * 2) * 2 + 0] = r0; b[(nb * 2) * 2 + 1] = r1;
            b[(nb * 2 + 1) * 2 + 0] = r2; b[(nb * 2 + 1) * 2 + 1] = r3;
        }
    };
    auto mmaAll = [&](const uint32_t* a, const uint32_t* b) {
#pragma unroll
        for (int mi = 0; mi < 4; mi++)
#pragma unroll
            for (int nj = 0; nj < 8; nj++)
                mma16816(c[mi][nj], a + mi * 4, b + nj * 2);
    };

    // register-direct epilogue: no smem, no block sync; overlaps in-flight loads
    auto epilogue = [&](int tile) {
        int rbase = row0 + tile * 128 + wm * 64;
        const float* bp = bias + (size_t)e * NT + n0 + wn * 64;
        int g = lane >> 2, tg = lane & 3;
#pragma unroll
        for (int mi = 0; mi < 4; mi++) {
#pragma unroll
            for (int nj = 0; nj < 8; nj++) {
                int col = nj * 8 + tg * 2;
                float b0 = __ldg(bp + col), b1 = __ldg(bp + col + 1);
                float v0 = c[mi][nj][0] + b0, v1 = c[mi][nj][1] + b1;
                float v2 = c[mi][nj][2] + b0, v3 = c[mi][nj][3] + b1;
                if (RELU) {
                    v0 = fmaxf(v0, 0.f); v1 = fmaxf(v1, 0.f);
                    v2 = fmaxf(v2, 0.f); v3 = fmaxf(v3, 0.f);
                }
                int r0 = rbase + mi * 16 + g;
                size_t cbase = (size_t)e * CAP;
                size_t coloff = (size_t)n0 + wn * 64 + col;
                __half* dst = RELU ? g_h : g_y;
                if (r0 < cnt) {
                    __half2 h = __floats2half2_rn(v0, v1);
                    *(uint32_t*)(dst + (cbase + r0) * NT + coloff) = *(uint32_t*)&h;
                }
                if (r0 + 8 < cnt) {
                    __half2 h = __floats2half2_rn(v2, v3);
                    *(uint32_t*)(dst + (cbase + r0 + 8) * NT + coloff) = *(uint32_t*)&h;
                }
            }
        }
#pragma unroll
        for (int i = 0; i < 4; i++)
#pragma unroll
            for (int j = 0; j < 8; j++)
#pragma unroll
                for (int q = 0; q < 4; q++) c[i][j][q] = 0.f;
    };

    const int TT = TILES * NKT;
    loadStage(0); cp_commit();
    loadStage(1); cp_commit();

    for (int gq = 0; gq < TT; gq++) {
        if (gq + 1 < TT) cp_wait<1>(); else cp_wait<0>();
        __syncthreads();
        if (gq + 2 < TT) { loadStage(gq + 2); cp_commit(); }

        int stg = gq % NSTG;
        ldA(Ar[0], stg, 0); ldB(Br[0], stg, 0);
#pragma unroll
        for (int ks = 0; ks < 4; ks++) {
            if (ks < 3) {
                ldA(Ar[(ks + 1) & 1], stg, ks + 1);
                ldB(Br[(ks + 1) & 1], stg, ks + 1);
            }
            mmaAll(Ar[ks & 1], Br[ks & 1]);
        }
        if ((gq & (NKT - 1)) == NKT - 1) epilogue(gq / NKT);
    }
}

// ---------------- weighted combine (fp16 y, fp32 accumulate) ----------------
__global__ void k_combine(float* __restrict__ out) {
    int n = blockIdx.x;
    int c = threadIdx.x * 4;
    int   s0 = g_slot[n * TOPK + 0], s1 = g_slot[n * TOPK + 1];
    int   s2 = g_slot[n * TOPK + 2], s3 = g_slot[n * TOPK + 3];
    float w0 = g_tw[n * TOPK + 0],  w1 = g_tw[n * TOPK + 1];
    float w2 = g_tw[n * TOPK + 2],  w3 = g_tw[n * TOPK + 3];
    uint2 u0 = *(const uint2*)(g_y + (size_t)s0 * DOUT + c);
    uint2 u1 = *(const uint2*)(g_y + (size_t)s1 * DOUT + c);
    uint2 u2 = *(const uint2*)(g_y + (size_t)s2 * DOUT + c);
    uint2 u3 = *(const uint2*)(g_y + (size_t)s3 * DOUT + c);
    float2 a0 = __half22float2(*(__half2*)&u0.x), b0 = __half22float2(*(__half2*)&u0.y);
    float2 a1 = __half22float2(*(__half2*)&u1.x), b1 = __half22float2(*(__half2*)&u1.y);
    float2 a2 = __half22float2(*(__half2*)&u2.x), b2 = __half22float2(*(__half2*)&u2.y);
    float2 a3 = __half22float2(*(__half2*)&u3.x), b3 = __half22float2(*(__half2*)&u3.y);
    float4 r;
    r.x = w0 * a0.x + w1 * a1.x + w2 * a2.x + w3 * a3.x;
    r.y = w0 * a0.y + w1 * a1.y + w2 * a2.y + w3 * a3.y;
    r.z = w0 * b0.x + w1 * b1.x + w2 * b2.x + w3 * b3.x;
    r.w = w0 * b0.y + w1 * b1.y + w2 * b2.y + w3 * b3.y;
    *(float4*)(out + (size_t)n * DOUT + c) = r;
}

// ---------------- launch ----------------
extern "C" void kernel_launch(void* const* d_in, const int* in_sizes, int n_in,
                              void* d_out, int out_size) {
    const float* x  = (const float*)d_in[0];
    const float* W1 = (const float*)d_in[1];
    const float* b1 = (const float*)d_in[2];
    const float* W2 = (const float*)d_in[3];
    const float* b2 = (const float*)d_in[4];
    const float* Wg = (const float*)d_in[5];
    const float* bg = (const float*)d_in[6];
    float* out = (float*)d_out;

    const int SMEM_GATE = DIN * NEXP * (int)sizeof(float);

    cudaFuncSetAttribute((const void*)k_gate,
                         cudaFuncAttributeMaxDynamicSharedMemorySize, SMEM_GATE);
    cudaFuncSetAttribute((const void*)k_gemm_h<DIN, DHID, true, true, 2>,
                         cudaFuncAttributeMaxDynamicSharedMemorySize, SMEM_GM);
    cudaFuncSetAttribute((const void*)k_gemm_h<DHID, DOUT, false, false, 1>,
                         cudaFuncAttributeMaxDynamicSharedMemorySize, SMEM_GM);

    __half* w1h = nullptr; cudaGetSymbolAddress((void**)&w1h, g_W1h);
    __half* w2h = nullptr; cudaGetSymbolAddress((void**)&w2h, g_W2h);

    // harness prepends 2 launches; ncu -s 5 -c 1 profiles our launch #3 = gemm1
    k_zero<<<1, 32>>>();
    k_gate<<<N_TOKS / 8, 256, SMEM_GATE>>>(x, Wg, bg);
    k_conv<<<(int)((NX + NW1 + NW2) / (256 * 8)), 256>>>(x, W1, W2);
    k_gemm_h<DIN, DHID, true, true, 2>
        <<<dim3(DHID / 128, CAP / 256, NEXP), 128, SMEM_GM>>>(w1h, b1);
    k_gemm_h<DHID, DOUT, false, false, 1>
        <<<dim3(DOUT / 128, CAP / 128, NEXP), 128, SMEM_GM>>>(w2h, b2);
    k_combine<<<N_TOKS, 256>>>(out);
}

// round 16
// speedup vs baseline: 1.0573x; 1.0032x over previous
#include <cuda_runtime.h>
#include <cuda_fp16.h>
#include <cstdint>
#include <cstddef>

#define N_TOKS  8192
#define DIN     1024
#define DHID    4096
#define DOUT    1024
#define NEXP    12
#define TOPK    4
#define CAP     4096

// ---------------- scratch (device globals) ----------------
__device__ int    g_cnt[NEXP];
__device__ int    g_tok[NEXP * CAP];
__device__ int    g_slot[N_TOKS * TOPK];
__device__ float  g_tw[N_TOKS * TOPK];
__device__ __half g_xh [(size_t)N_TOKS * DIN];
__device__ __half g_W1h[(size_t)NEXP * DIN * DHID];
__device__ __half g_W2h[(size_t)NEXP * DHID * DOUT];
__device__ __half g_h  [(size_t)NEXP * CAP * DHID];
__device__ __half g_y  [(size_t)NEXP * CAP * DOUT];

// ---------------- helpers ----------------
static __device__ __forceinline__ uint32_t sptr(const void* p) {
    return (uint32_t)__cvta_generic_to_shared(p);
}
static __device__ __forceinline__ void cp16(uint32_t s, const void* g) {
    asm volatile("cp.async.cg.shared.global [%0], [%1], 16;" :: "r"(s), "l"(g));
}
static __device__ __forceinline__ void cp_commit() {
    asm volatile("cp.async.commit_group;");
}
template <int N>
static __device__ __forceinline__ void cp_wait() {
    asm volatile("cp.async.wait_group %0;" :: "n"(N));
}
static __device__ __forceinline__ void ldsm4(uint32_t& r0, uint32_t& r1,
                                             uint32_t& r2, uint32_t& r3, uint32_t a) {
    asm volatile("ldmatrix.sync.aligned.m8n8.x4.shared.b16 {%0,%1,%2,%3}, [%4];"
                 : "=r"(r0), "=r"(r1), "=r"(r2), "=r"(r3) : "r"(a));
}
static __device__ __forceinline__ void ldsm4t(uint32_t& r0, uint32_t& r1,
                                              uint32_t& r2, uint32_t& r3, uint32_t a) {
    asm volatile("ldmatrix.sync.aligned.m8n8.x4.trans.shared.b16 {%0,%1,%2,%3}, [%4];"
                 : "=r"(r0), "=r"(r1), "=r"(r2), "=r"(r3) : "r"(a));
}
static __device__ __forceinline__ void mma16816(float* c, const uint32_t* a,
                                                const uint32_t* b) {
    asm volatile(
        "mma.sync.aligned.m16n8k16.row.col.f32.f16.f16.f32 "
        "{%0,%1,%2,%3}, {%4,%5,%6,%7}, {%8,%9}, {%0,%1,%2,%3};"
        : "+f"(c[0]), "+f"(c[1]), "+f"(c[2]), "+f"(c[3])
        : "r"(a[0]), "r"(a[1]), "r"(a[2]), "r"(a[3]), "r"(b[0]), "r"(b[1]));
}

// ---------------- fused W1/W2 fp32->fp16 conversion + counter zero ----------------
static constexpr size_t NW1 = (size_t)NEXP * DIN * DHID;
static constexpr size_t NW2 = (size_t)NEXP * DHID * DOUT;
__global__ void k_conv(const float* __restrict__ W1, const float* __restrict__ W2) {
    if (blockIdx.x == 0 && threadIdx.x < NEXP) g_cnt[threadIdx.x] = 0;
    size_t i = ((size_t)blockIdx.x * 256 + threadIdx.x) * 8;
    const float* in;
    __half* out;
    if (i < NW1) { in = W1 + i;         out = g_W1h + i; }
    else         { in = W2 + (i - NW1); out = g_W2h + (i - NW1); }
    float4 a = *(const float4*)(in);
    float4 b = *(const float4*)(in + 4);
    __half2 h0 = __floats2half2_rn(a.x, a.y);
    __half2 h1 = __floats2half2_rn(a.z, a.w);
    __half2 h2 = __floats2half2_rn(b.x, b.y);
    __half2 h3 = __floats2half2_rn(b.z, b.w);
    uint4 o;
    o.x = *(uint32_t*)&h0; o.y = *(uint32_t*)&h1;
    o.z = *(uint32_t*)&h2; o.w = *(uint32_t*)&h3;
    *(uint4*)(out) = o;
}

// ---------------- gate: logits, top-4, softmax, routing + x->fp16 ----------------
__global__ void k_gate(const float* __restrict__ x, const float* __restrict__ Wg,
                       const float* __restrict__ bg) {
    extern __shared__ float sWg[];
    __shared__ float sLog[8][NEXP];
    __shared__ int   sCnt[NEXP];
    __shared__ int   sBase[NEXP];
    __shared__ int   sE[8][TOPK];
    __shared__ int   sL[8][TOPK];
    __shared__ float sW[8][TOPK];

    int tid = threadIdx.x;
    for (int i = tid; i < DIN * NEXP / 4; i += 256)
        ((float4*)sWg)[i] = ((const float4*)Wg)[i];
    if (tid < NEXP) sCnt[tid] = 0;
    __syncthreads();

    int wp = tid >> 5, lane = tid & 31;
    int n = blockIdx.x * 8 + wp;

    float xv[32];
#pragma unroll
    for (int i = 0; i < 32; i++)
        xv[i] = x[(size_t)n * DIN + i * 32 + lane];

    // fused x -> fp16 (same RN conversion as before; coalesced 2B stores)
#pragma unroll
    for (int i = 0; i < 32; i++)
        g_xh[(size_t)n * DIN + i * 32 + lane] = __float2half_rn(xv[i]);

#pragma unroll
    for (int e = 0; e < NEXP; e++) {
        float p = 0.f;
#pragma unroll
        for (int i = 0; i < 32; i++)
            p += xv[i] * sWg[(i * 32 + lane) * NEXP + e];
#pragma unroll
        for (int o = 16; o > 0; o >>= 1)
            p += __shfl_xor_sync(0xffffffffu, p, o);
        if (lane == 0) sLog[wp][e] = p + bg[e];
    }
    __syncwarp();

    if (lane == 0) {
        float v[NEXP];
#pragma unroll
        for (int e = 0; e < NEXP; e++) v[e] = sLog[wp][e];
        float bv[TOPK]; int bi[TOPK];
#pragma unroll
        for (int k = 0; k < TOPK; k++) {
            float best = -1e30f; int bj = 0;
#pragma unroll
            for (int e = 0; e < NEXP; e++)
                if (v[e] > best) { best = v[e]; bj = e; }
            bv[k] = best; bi[k] = bj; v[bj] = -1e30f;
        }
        float m = bv[0], s = 0.f, ew[TOPK];
#pragma unroll
        for (int k = 0; k < TOPK; k++) { ew[k] = expf(bv[k] - m); s += ew[k]; }
        float inv = 1.0f / s;
#pragma unroll
        for (int k = 0; k < TOPK; k++) {
            int e = bi[k];
            int loc = atomicAdd(&sCnt[e], 1);
            sE[wp][k] = e; sL[wp][k] = loc; sW[wp][k] = ew[k] * inv;
        }
    }
    __syncthreads();
    if (tid < NEXP) sBase[tid] = atomicAdd(&g_cnt[tid], sCnt[tid]);
    __syncthreads();
    if (lane == 0) {
#pragma unroll
        for (int k = 0; k < TOPK; k++) {
            int e = sE[wp][k];
            int idx = sBase[e] + sL[wp][k];
            g_tok[e * CAP + idx] = n;
            g_slot[n * TOPK + k] = e * CAP + idx;
            g_tw[n * TOPK + k]   = sW[wp][k];
        }
    }
}

// ---- fp16 mma.sync grouped GEMM: TILES M-tiles/CTA, 128x128x64, 128 thr, 3-stage ring ----
static constexpr int NSTG     = 3;
static constexpr int AS_LD    = 72;                 // halves
static constexpr int BS_LD    = 136;                // halves
static constexpr int AS_STG_H = 128 * AS_LD;
static constexpr int BS_STG_H = 64 * BS_LD;
static constexpr int AS_STG_B = AS_STG_H * 2;       // 18432
static constexpr int BS_STG_B = BS_STG_H * 2;       // 17408
static constexpr int AS_OFF   = 0;
static constexpr int BS_OFF   = NSTG * AS_STG_B;                // 55296
static constexpr int TOK_OFF  = BS_OFF + NSTG * BS_STG_B;       // 107520
static constexpr int SMEM_GM  = TOK_OFF + 1024 + 256;           // 108800 (2 CTA/SM)

template <int KD, int NT, bool GATHER, bool RELU, int TILES>
__global__ void __launch_bounds__(128, 2)
k_gemm_h(const __half* __restrict__ W, const float* __restrict__ bias) {
    extern __shared__ char smem[];
    __half* As   = (__half*)(smem + AS_OFF);
    __half* Bs   = (__half*)(smem + BS_OFF);
    int*    sTok = (int*)(smem + TOK_OFF);

    int e    = blockIdx.z;
    int cnt  = g_cnt[e];
    int row0 = blockIdx.y * (128 * TILES);
    if (row0 >= cnt) return;
    int n0   = blockIdx.x * 128;
    int tid  = threadIdx.x;

    const __half* Ain = GATHER ? (const __half*)g_xh : (const __half*)g_h;

    if (GATHER) {
#pragma unroll
        for (int t = 0; t < TILES; t++) {
            int r = row0 + t * 128 + tid;
            sTok[t * 128 + tid] = (r < cnt) ? g_tok[e * CAP + r] : g_tok[e * CAP];
        }
        __syncthreads();
    }

    const __half* Wp = W + (size_t)e * KD * NT + n0;

    constexpr int NKT = KD / 64;
    auto loadStage = [&](int gq) {
        int buf  = gq % NSTG;
        int tile = gq / NKT;
        int kt   = gq % NKT;
        int k0   = kt * 64;
        int rb   = row0 + tile * 128;
#pragma unroll
        for (int i = 0; i < 8; i++) {
            int c = tid + i * 128;
            int r = c >> 3, sg = (c & 7) * 8;
            const __half* g = GATHER
                ? (Ain + (size_t)sTok[tile * 128 + r] * KD + k0 + sg)
                : (Ain + ((size_t)e * CAP + rb + r) * KD + k0 + sg);
            cp16(sptr(As + buf * AS_STG_H + r * AS_LD + sg), g);
        }
#pragma unroll
        for (int i = 0; i < 8; i++) {
            int c = tid + i * 128;
            int r = c >> 4, col = (c & 15) * 8;
            cp16(sptr(Bs + buf * BS_STG_H + r * BS_LD + col),
                 Wp + (size_t)(k0 + r) * NT + col);
        }
    };

    int wp = tid >> 5, lane = tid & 31;
    int wm = wp & 1, wn = wp >> 1;       // 2x2 warp grid; warp tile 64x64

    uint32_t aBase = sptr(As) +
        (uint32_t)(((wm * 64 + (lane & 15)) * AS_LD + (lane >> 4) * 8) * 2);
    uint32_t bBase = sptr(Bs) +
        (uint32_t)(((((lane >> 3) & 1) * 8 + (lane & 7)) * BS_LD
                    + wn * 64 + (lane >> 4) * 8) * 2);

    float c[4][8][4];
#pragma unroll
    for (int i = 0; i < 4; i++)
#pragma unroll
        for (int j = 0; j < 8; j++)
#pragma unroll
            for (int q = 0; q < 4; q++) c[i][j][q] = 0.f;

    uint32_t Ar[2][16], Br[2][16];

    auto ldA = [&](uint32_t* a, int buf, int ks) {
        uint32_t base = aBase + buf * AS_STG_B + ks * 32;
#pragma unroll
        for (int mi = 0; mi < 4; mi++)
            ldsm4(a[mi * 4 + 0], a[mi * 4 + 1], a[mi * 4 + 2], a[mi * 4 + 3],
                  base + mi * 16 * AS_LD * 2);
    };
    auto ldB = [&](uint32_t* b, int buf, int ks) {
        uint32_t base = bBase + buf * BS_STG_B + ks * 16 * BS_LD * 2;
#pragma unroll
        for (int nb = 0; nb < 4; nb++) {
            uint32_t r0, r1, r2, r3;
            ldsm4t(r0, r1, r2, r3, base + nb * 32);
            b[(nb * 2) * 2 + 0] = r0; b[(nb * 2) * 2 + 1] = r1;
            b[(nb * 2 + 1) * 2 + 0] = r2; b[(nb * 2 + 1) * 2 + 1] = r3;
        }
    };
    auto mmaAll = [&](const uint32_t* a, const uint32_t* b) {
#pragma unroll
        for (int mi = 0; mi < 4; mi++)
#pragma unroll
            for (int nj = 0; nj < 8; nj++)
                mma16816(c[mi][nj], a + mi * 4, b + nj * 2);
    };

    auto epilogue = [&](int tile) {
        int rbase = row0 + tile * 128 + wm * 64;
        const float* bp = bias + (size_t)e * NT + n0 + wn * 64;
        int g = lane >> 2, tg = lane & 3;
#pragma unroll
        for (int mi = 0; mi < 4; mi++) {
#pragma unroll
            for (int nj = 0; nj < 8; nj++) {
                int col = nj * 8 + tg * 2;
                float b0 = __ldg(bp + col), b1 = __ldg(bp + col + 1);
                float v0 = c[mi][nj][0] + b0, v1 = c[mi][nj][1] + b1;
                float v2 = c[mi][nj][2] + b0, v3 = c[mi][nj][3] + b1;
                if (RELU) {
                    v0 = fmaxf(v0, 0.f); v1 = fmaxf(v1, 0.f);
                    v2 = fmaxf(v2, 0.f); v3 = fmaxf(v3, 0.f);
                }
                int r0 = rbase + mi * 16 + g;
                size_t cbase = (size_t)e * CAP;
                size_t coloff = (size_t)n0 + wn * 64 + col;
                __half* dst = RELU ? g_h : g_y;
                if (r0 < cnt) {
                    __half2 h = __floats2half2_rn(v0, v1);
                    *(uint32_t*)(dst + (cbase + r0) * NT + coloff) = *(uint32_t*)&h;
                }
                if (r0 + 8 < cnt) {
                    __half2 h = __floats2half2_rn(v2, v3);
                    *(uint32_t*)(dst + (cbase + r0 + 8) * NT + coloff) = *(uint32_t*)&h;
                }
            }
        }
#pragma unroll
        for (int i = 0; i < 4; i++)
#pragma unroll
            for (int j = 0; j < 8; j++)
#pragma unroll
                for (int q = 0; q < 4; q++) c[i][j][q] = 0.f;
    };

    const int TT = TILES * NKT;
    loadStage(0); cp_commit();
    loadStage(1); cp_commit();

    for (int gq = 0; gq < TT; gq++) {
        if (gq + 1 < TT) cp_wait<1>(); else cp_wait<0>();
        __syncthreads();
        if (gq + 2 < TT) { loadStage(gq + 2); cp_commit(); }

        int stg = gq % NSTG;
        ldA(Ar[0], stg, 0); ldB(Br[0], stg, 0);
#pragma unroll
        for (int ks = 0; ks < 4; ks++) {
            if (ks < 3) {
                ldA(Ar[(ks + 1) & 1], stg, ks + 1);
                ldB(Br[(ks + 1) & 1], stg, ks + 1);
            }
            mmaAll(Ar[ks & 1], Br[ks & 1]);
        }
        if ((gq & (NKT - 1)) == NKT - 1) epilogue(gq / NKT);
    }
}

// ---------------- weighted combine (fp16 y, fp32 accumulate) ----------------
__global__ void k_combine(float* __restrict__ out) {
    int n = blockIdx.x;
    int c = threadIdx.x * 4;
    int   s0 = g_slot[n * TOPK + 0], s1 = g_slot[n * TOPK + 1];
    int   s2 = g_slot[n * TOPK + 2], s3 = g_slot[n * TOPK + 3];
    float w0 = g_tw[n * TOPK + 0],  w1 = g_tw[n * TOPK + 1];
    float w2 = g_tw[n * TOPK + 2],  w3 = g_tw[n * TOPK + 3];
    uint2 u0 = *(const uint2*)(g_y + (size_t)s0 * DOUT + c);
    uint2 u1 = *(const uint2*)(g_y + (size_t)s1 * DOUT + c);
    uint2 u2 = *(const uint2*)(g_y + (size_t)s2 * DOUT + c);
    uint2 u3 = *(const uint2*)(g_y + (size_t)s3 * DOUT + c);
    float2 a0 = __half22float2(*(__half2*)&u0.x), b0 = __half22float2(*(__half2*)&u0.y);
    float2 a1 = __half22float2(*(__half2*)&u1.x), b1 = __half22float2(*(__half2*)&u1.y);
    float2 a2 = __half22float2(*(__half2*)&u2.x), b2 = __half22float2(*(__half2*)&u2.y);
    float2 a3 = __half22float2(*(__half2*)&u3.x), b3 = __half22float2(*(__half2*)&u3.y);
    float4 r;
    r.x = w0 * a0.x + w1 * a1.x + w2 * a2.x + w3 * a3.x;
    r.y = w0 * a0.y + w1 * a1.y + w2 * a2.y + w3 * a3.y;
    r.z = w0 * b0.x + w1 * b1.x + w2 * b2.x + w3 * b3.x;
    r.w = w0 * b0.y + w1 * b1.y + w2 * b2.y + w3 * b3.y;
    *(float4*)(out + (size_t)n * DOUT + c) = r;
}

// ---------------- launch ----------------
extern "C" void kernel_launch(void* const* d_in, const int* in_sizes, int n_in,
                              void* d_out, int out_size) {
    const float* x  = (const float*)d_in[0];
    const float* W1 = (const float*)d_in[1];
    const float* b1 = (const float*)d_in[2];
    const float* W2 = (const float*)d_in[3];
    const float* b2 = (const float*)d_in[4];
    const float* Wg = (const float*)d_in[5];
    const float* bg = (const float*)d_in[6];
    float* out = (float*)d_out;

    const int SMEM_GATE = DIN * NEXP * (int)sizeof(float);

    cudaFuncSetAttribute((const void*)k_gate,
                         cudaFuncAttributeMaxDynamicSharedMemorySize, SMEM_GATE);
    cudaFuncSetAttribute((const void*)k_gemm_h<DIN, DHID, true, true, 2>,
                         cudaFuncAttributeMaxDynamicSharedMemorySize, SMEM_GM);
    cudaFuncSetAttribute((const void*)k_gemm_h<DHID, DOUT, false, false, 1>,
                         cudaFuncAttributeMaxDynamicSharedMemorySize, SMEM_GM);

    __half* w1h = nullptr; cudaGetSymbolAddress((void**)&w1h, g_W1h);
    __half* w2h = nullptr; cudaGetSymbolAddress((void**)&w2h, g_W2h);

    // launches: conv(0), gate(1), gemm1(2), gemm2(3), combine(4)
    // harness prepends 2; ncu -s 5 -c 1 profiles our index 3 = gemm2 (first look!)
    k_conv<<<(int)((NW1 + NW2) / (256 * 8)), 256>>>(W1, W2);
    k_gate<<<N_TOKS / 8, 256, SMEM_GATE>>>(x, Wg, bg);
    k_gemm_h<DIN, DHID, true, true, 2>
        <<<dim3(DHID / 128, CAP / 256, NEXP), 128, SMEM_GM>>>(w1h, b1);
    k_gemm_h<DHID, DOUT, false, false, 1>
        <<<dim3(DOUT / 128, CAP / 128, NEXP), 128, SMEM_GM>>>(w2h, b2);
    k_combine<<<N_TOKS, 256>>>(out);
}